// round 5
// baseline (speedup 1.0000x reference)
#include <cuda_runtime.h>
#include <cstdint>

// Causal MHA, B=2, L=2048, H=16, E=64, fp32; reference scales scores by sqrt(E)=8.
// tf32 mma.sync flash-attention, error-compensated:
//   QK^T: 3xTF32 (qh*kh + ql*kh + qh*kl); PV: split-A (ph*v + pl*v).
// R4: cp.async double-buffered raw-f32 K/V tiles (distance-2 pipeline);
// tf32 conversion + hi/lo split done at fragment-load time in the consumer.

#define NT 256
#define BM 128
#define BN 64
#define ED 64
#define KST 68   // K smem row stride (floats): conflict-free B-frag loads
#define VST 72   // V smem row stride (floats): conflict-free B-frag loads

static constexpr int B_ = 2, L_ = 2048, H_ = 16;
static constexpr int RS = H_ * ED;                               // 1024 floats/row
static constexpr int BUF_FLOATS = BN * KST + BN * VST;           // 8960
static constexpr int SMEM_BYTES = 2 * BUF_FLOATS * 4;            // 71680 B

__device__ __forceinline__ uint32_t f2tf(float f) {
    uint32_t r;
    asm("cvt.rna.tf32.f32 %0, %1;" : "=r"(r) : "f"(f));
    return r;
}

__device__ __forceinline__ void mma_tf32(float c[4],
                                         uint32_t a0, uint32_t a1, uint32_t a2, uint32_t a3,
                                         uint32_t b0, uint32_t b1) {
    asm volatile(
        "mma.sync.aligned.m16n8k8.row.col.f32.tf32.tf32.f32 "
        "{%0,%1,%2,%3}, {%4,%5,%6,%7}, {%8,%9}, {%0,%1,%2,%3};"
        : "+f"(c[0]), "+f"(c[1]), "+f"(c[2]), "+f"(c[3])
        : "r"(a0), "r"(a1), "r"(a2), "r"(a3), "r"(b0), "r"(b1));
}

__device__ __forceinline__ void cp16(uint32_t dst, const float* src) {
    asm volatile("cp.async.cg.shared.global [%0], [%1], 16;\n"
                 :: "r"(dst), "l"(src));
}

__global__ __launch_bounds__(NT, 1) void attn_kernel(
    const float* __restrict__ Q, const float* __restrict__ K,
    const float* __restrict__ V, float* __restrict__ O)
{
    extern __shared__ float smf[];
    float* Kb[2]; float* Vb[2];
    Kb[0] = smf;
    Vb[0] = Kb[0] + BN * KST;
    Kb[1] = Vb[0] + BN * VST;
    Vb[1] = Kb[1] + BN * KST;

    const int tid  = threadIdx.x;
    const int lane = tid & 31;
    const int w    = tid >> 5;
    const int r    = lane >> 2;               // 0..7
    const int c    = lane & 3;                // 0..3
    const int qt = blockIdx.x, h = blockIdx.y, b = blockIdx.z;
    const int q0 = qt * BM;
    const int m_lo = q0 + w * 16 + r;
    const size_t base = ((size_t)b * L_ * H_ + h) * ED;
    const float* Qp = Q + base;
    const float* Kp = K + base;
    const float* Vp = V + base;
    float*       Op = O + base;

    // staging addresses for this thread (4 float4 slots per tile per tensor)
    const int srr[4] = { (tid + 0*NT) >> 4, (tid + 1*NT) >> 4,
                         (tid + 2*NT) >> 4, (tid + 3*NT) >> 4 };
    const int scc = (tid & 15) * 4;

    // ---- Q A-fragments, x8 scale, hi/lo tf32 split, resident ----
    uint32_t qh[8][4], ql[8][4];
    #pragma unroll
    for (int kk = 0; kk < 8; ++kk) {
        const float* p = Qp + (size_t)m_lo * RS + kk * 8 + c;
        float f0 = 8.f * p[0];
        float f1 = 8.f * p[8 * RS];
        float f2 = 8.f * p[4];
        float f3 = 8.f * p[8 * RS + 4];
        qh[kk][0] = f2tf(f0); ql[kk][0] = f2tf(f0 - __uint_as_float(qh[kk][0]));
        qh[kk][1] = f2tf(f1); ql[kk][1] = f2tf(f1 - __uint_as_float(qh[kk][1]));
        qh[kk][2] = f2tf(f2); ql[kk][2] = f2tf(f2 - __uint_as_float(qh[kk][2]));
        qh[kk][3] = f2tf(f3); ql[kk][3] = f2tf(f3 - __uint_as_float(qh[kk][3]));
    }

    float acc[8][4];
    #pragma unroll
    for (int j = 0; j < 8; ++j)
        #pragma unroll
        for (int i = 0; i < 4; ++i) acc[j][i] = 0.f;

    float mr0 = -1e30f, mr1 = -1e30f, l0 = 0.f, l1 = 0.f;

    const int nTiles = 2 * qt + 2;            // >= 2 always

    // ---- stage helper (issues 8 cp.async + commit) ----
    auto stage = [&](int kt, float* Kd, float* Vd) {
        const int k0 = kt * BN;
        #pragma unroll
        for (int t = 0; t < 4; ++t) {
            const int rr = srr[t];
            cp16((uint32_t)__cvta_generic_to_shared(&Kd[rr * KST + scc]),
                 Kp + (size_t)(k0 + rr) * RS + scc);
            cp16((uint32_t)__cvta_generic_to_shared(&Vd[rr * VST + scc]),
                 Vp + (size_t)(k0 + rr) * RS + scc);
        }
        asm volatile("cp.async.commit_group;\n" ::: "memory");
    };

    stage(0, Kb[0], Vb[0]);
    stage(1, Kb[1], Vb[1]);

    for (int kt = 0; kt < nTiles; ++kt) {
        const int k0 = kt * BN;
        const float* Kw = Kb[kt & 1];
        const float* Vw = Vb[kt & 1];

        if (kt + 1 < nTiles)
            asm volatile("cp.async.wait_group 1;\n" ::: "memory");
        else
            asm volatile("cp.async.wait_group 0;\n" ::: "memory");
        __syncthreads();

        // ---- S = (8Q) K^T, 3xTF32; K hi/lo built from raw smem ----
        float s[8][4];
        #pragma unroll
        for (int j = 0; j < 8; ++j)
            #pragma unroll
            for (int i = 0; i < 4; ++i) s[j][i] = 0.f;

        #pragma unroll
        for (int kk = 0; kk < 8; ++kk) {
            #pragma unroll
            for (int j = 0; j < 8; ++j) {
                const float* kp = &Kw[(j * 8 + r) * KST + kk * 8 + c];
                float k0f = kp[0], k1f = kp[4];
                uint32_t bh0 = f2tf(k0f), bh1 = f2tf(k1f);
                uint32_t bl0 = f2tf(k0f - __uint_as_float(bh0));
                uint32_t bl1 = f2tf(k1f - __uint_as_float(bh1));
                mma_tf32(s[j], qh[kk][0], qh[kk][1], qh[kk][2], qh[kk][3], bh0, bh1);
                mma_tf32(s[j], ql[kk][0], ql[kk][1], ql[kk][2], ql[kk][3], bh0, bh1);
                mma_tf32(s[j], qh[kk][0], qh[kk][1], qh[kk][2], qh[kk][3], bl0, bl1);
            }
        }

        // ---- causal mask (only tiles that can touch the diagonal) ----
        if (kt >= 2 * qt) {
            #pragma unroll
            for (int j = 0; j < 8; ++j) {
                int n = k0 + j * 8 + 2 * c;
                if (n     > m_lo)     s[j][0] = -1e30f;
                if (n + 1 > m_lo)     s[j][1] = -1e30f;
                if (n     > m_lo + 8) s[j][2] = -1e30f;
                if (n + 1 > m_lo + 8) s[j][3] = -1e30f;
            }
        }

        // ---- online softmax (rows r and r+8) ----
        float mx0 = -1e30f, mx1 = -1e30f;
        #pragma unroll
        for (int j = 0; j < 8; ++j) {
            mx0 = fmaxf(mx0, fmaxf(s[j][0], s[j][1]));
            mx1 = fmaxf(mx1, fmaxf(s[j][2], s[j][3]));
        }
        mx0 = fmaxf(mx0, __shfl_xor_sync(0xffffffffu, mx0, 1));
        mx0 = fmaxf(mx0, __shfl_xor_sync(0xffffffffu, mx0, 2));
        mx1 = fmaxf(mx1, __shfl_xor_sync(0xffffffffu, mx1, 1));
        mx1 = fmaxf(mx1, __shfl_xor_sync(0xffffffffu, mx1, 2));

        float mn0 = fmaxf(mr0, mx0), mn1 = fmaxf(mr1, mx1);
        float al0 = __expf(mr0 - mn0), al1 = __expf(mr1 - mn1);
        float sum0 = 0.f, sum1 = 0.f;
        #pragma unroll
        for (int j = 0; j < 8; ++j) {
            s[j][0] = __expf(s[j][0] - mn0);
            s[j][1] = __expf(s[j][1] - mn0);
            s[j][2] = __expf(s[j][2] - mn1);
            s[j][3] = __expf(s[j][3] - mn1);
            sum0 += s[j][0] + s[j][1];
            sum1 += s[j][2] + s[j][3];
        }
        sum0 += __shfl_xor_sync(0xffffffffu, sum0, 1);
        sum0 += __shfl_xor_sync(0xffffffffu, sum0, 2);
        sum1 += __shfl_xor_sync(0xffffffffu, sum1, 1);
        sum1 += __shfl_xor_sync(0xffffffffu, sum1, 2);

        l0 = l0 * al0 + sum0;
        l1 = l1 * al1 + sum1;
        mr0 = mn0; mr1 = mn1;

        #pragma unroll
        for (int j = 0; j < 8; ++j) {
            acc[j][0] *= al0; acc[j][1] *= al0;
            acc[j][2] *= al1; acc[j][3] *= al1;
        }

        // ---- O += P V : re-fragment P via shuffles, split-A tf32 ----
        const int src_lo = (lane & ~3) | (c >> 1);
        const int src_hi = src_lo + 2;
        const bool odd = (c & 1);
        #pragma unroll
        for (int kk = 0; kk < 8; ++kk) {
            float v00 = __shfl_sync(0xffffffffu, s[kk][0], src_lo);
            float v01 = __shfl_sync(0xffffffffu, s[kk][1], src_lo);
            float v10 = __shfl_sync(0xffffffffu, s[kk][0], src_hi);
            float v11 = __shfl_sync(0xffffffffu, s[kk][1], src_hi);
            float v20 = __shfl_sync(0xffffffffu, s[kk][2], src_lo);
            float v21 = __shfl_sync(0xffffffffu, s[kk][3], src_lo);
            float v30 = __shfl_sync(0xffffffffu, s[kk][2], src_hi);
            float v31 = __shfl_sync(0xffffffffu, s[kk][3], src_hi);
            float p0 = odd ? v01 : v00;
            float p1 = odd ? v21 : v20;
            float p2 = odd ? v11 : v10;
            float p3 = odd ? v31 : v30;
            uint32_t ph0 = f2tf(p0), pl0 = f2tf(p0 - __uint_as_float(ph0));
            uint32_t ph1 = f2tf(p1), pl1 = f2tf(p1 - __uint_as_float(ph1));
            uint32_t ph2 = f2tf(p2), pl2 = f2tf(p2 - __uint_as_float(ph2));
            uint32_t ph3 = f2tf(p3), pl3 = f2tf(p3 - __uint_as_float(ph3));
            #pragma unroll
            for (int jj = 0; jj < 8; ++jj) {
                float vb0 = Vw[(kk * 8 + c) * VST + jj * 8 + r];
                float vb1 = Vw[(kk * 8 + 4 + c) * VST + jj * 8 + r];
                uint32_t b0 = f2tf(vb0), b1 = f2tf(vb1);
                mma_tf32(acc[jj], ph0, ph1, ph2, ph3, b0, b1);
                mma_tf32(acc[jj], pl0, pl1, pl2, pl3, b0, b1);
            }
        }

        __syncthreads();                      // all warps done reading buf[kt&1]
        if (kt + 2 < nTiles)
            stage(kt + 2, Kb[kt & 1], Vb[kt & 1]);
    }

    // ---- epilogue ----
    const float inv0 = 1.f / l0, inv1 = 1.f / l1;
    #pragma unroll
    for (int jj = 0; jj < 8; ++jj) {
        float2 o0 = { acc[jj][0] * inv0, acc[jj][1] * inv0 };
        float2 o1 = { acc[jj][2] * inv1, acc[jj][3] * inv1 };
        *reinterpret_cast<float2*>(Op + (size_t)m_lo * RS + jj * 8 + 2 * c) = o0;
        *reinterpret_cast<float2*>(Op + (size_t)(m_lo + 8) * RS + jj * 8 + 2 * c) = o1;
    }
}

extern "C" void kernel_launch(void* const* d_in, const int* in_sizes, int n_in,
                              void* d_out, int out_size)
{
    const float* Q = (const float*)d_in[0];
    const float* K = (const float*)d_in[1];
    const float* V = (const float*)d_in[2];
    // d_in[3] = attn_mask (causal triu(k=1)) — applied analytically in-kernel.
    float* O = (float*)d_out;

    cudaFuncSetAttribute(attn_kernel, cudaFuncAttributeMaxDynamicSharedMemorySize,
                         SMEM_BYTES);
    dim3 grid(L_ / BM, H_, B_);   // 16 x 16 x 2
    attn_kernel<<<grid, NT, SMEM_BYTES>>>(Q, K, V, O);
}

// round 6
// speedup vs baseline: 1.1528x; 1.1528x over previous
#include <cuda_runtime.h>
#include <cstdint>

// Causal MHA, B=2, L=2048, H=16, E=64, fp32; reference scales scores by sqrt(E)=8.
// tf32 mma.sync flash-attention, error-compensated:
//   QK^T: 3xTF32 (qh*kh + ql*kh + qh*kl); PV: split-A (ph*v + pl*v).
// R5: cp.async double-buffers RAW K/V; a once-per-tile convert pass builds
// Kh/Kl/Vh in smem (conversion NOT in the MMA loop); softmax in log2 domain.

#define NT 256
#define BM 128
#define BN 64
#define ED 64
#define RST 68   // raw K/V smem row stride
#define KST 68   // converted K smem row stride (conflict-free B-frag loads)
#define VST 72   // converted V smem row stride (conflict-free B-frag loads)

static constexpr int B_ = 2, L_ = 2048, H_ = 16;
static constexpr int RS = H_ * ED;                         // 1024 floats/row
static constexpr int RAW_FLOATS = 4 * BN * RST;            // 2 bufs x (K+V)
static constexpr int CONV_FLOATS = 2 * BN * KST + BN * VST;
static constexpr int SMEM_BYTES = (RAW_FLOATS + CONV_FLOATS) * 4;   // 122880 B

__device__ __forceinline__ uint32_t f2tf(float f) {
    uint32_t r;
    asm("cvt.rna.tf32.f32 %0, %1;" : "=r"(r) : "f"(f));
    return r;
}

__device__ __forceinline__ float ex2(float x) {
    float y;
    asm("ex2.approx.f32 %0, %1;" : "=f"(y) : "f"(x));
    return y;
}

__device__ __forceinline__ void mma_tf32(float c[4],
                                         uint32_t a0, uint32_t a1, uint32_t a2, uint32_t a3,
                                         uint32_t b0, uint32_t b1) {
    asm volatile(
        "mma.sync.aligned.m16n8k8.row.col.f32.tf32.tf32.f32 "
        "{%0,%1,%2,%3}, {%4,%5,%6,%7}, {%8,%9}, {%0,%1,%2,%3};"
        : "+f"(c[0]), "+f"(c[1]), "+f"(c[2]), "+f"(c[3])
        : "r"(a0), "r"(a1), "r"(a2), "r"(a3), "r"(b0), "r"(b1));
}

__device__ __forceinline__ void cp16(uint32_t dst, const float* src) {
    asm volatile("cp.async.cg.shared.global [%0], [%1], 16;\n"
                 :: "r"(dst), "l"(src));
}

__global__ __launch_bounds__(NT, 1) void attn_kernel(
    const float* __restrict__ Q, const float* __restrict__ K,
    const float* __restrict__ V, float* __restrict__ O)
{
    extern __shared__ float smf[];
    float* rawK[2]; float* rawV[2];
    rawK[0] = smf;
    rawV[0] = rawK[0] + BN * RST;
    rawK[1] = rawV[0] + BN * RST;
    rawV[1] = rawK[1] + BN * RST;
    uint32_t* Kh = reinterpret_cast<uint32_t*>(rawV[1] + BN * RST);
    uint32_t* Kl = Kh + BN * KST;
    uint32_t* Vh = Kl + BN * KST;

    const int tid  = threadIdx.x;
    const int lane = tid & 31;
    const int w    = tid >> 5;
    const int r    = lane >> 2;               // 0..7
    const int c    = lane & 3;                // 0..3
    const int qt = blockIdx.x, h = blockIdx.y, b = blockIdx.z;
    const int q0 = qt * BM;
    const int m_lo = q0 + w * 16 + r;
    const size_t base = ((size_t)b * L_ * H_ + h) * ED;
    const float* Qp = Q + base;
    const float* Kp = K + base;
    const float* Vp = V + base;
    float*       Op = O + base;

    const int srr[4] = { (tid + 0*NT) >> 4, (tid + 1*NT) >> 4,
                         (tid + 2*NT) >> 4, (tid + 3*NT) >> 4 };
    const int scc = (tid & 15) * 4;

    // ---- Q A-fragments: scale 8*log2(e), hi/lo tf32 split, resident ----
    const float QS = 8.f * 1.4426950408889634f;
    uint32_t qh[8][4], ql[8][4];
    #pragma unroll
    for (int kk = 0; kk < 8; ++kk) {
        const float* p = Qp + (size_t)m_lo * RS + kk * 8 + c;
        float f0 = QS * p[0];
        float f1 = QS * p[8 * RS];
        float f2 = QS * p[4];
        float f3 = QS * p[8 * RS + 4];
        qh[kk][0] = f2tf(f0); ql[kk][0] = f2tf(f0 - __uint_as_float(qh[kk][0]));
        qh[kk][1] = f2tf(f1); ql[kk][1] = f2tf(f1 - __uint_as_float(qh[kk][1]));
        qh[kk][2] = f2tf(f2); ql[kk][2] = f2tf(f2 - __uint_as_float(qh[kk][2]));
        qh[kk][3] = f2tf(f3); ql[kk][3] = f2tf(f3 - __uint_as_float(qh[kk][3]));
    }

    float acc[8][4];
    #pragma unroll
    for (int j = 0; j < 8; ++j)
        #pragma unroll
        for (int i = 0; i < 4; ++i) acc[j][i] = 0.f;

    float mr0 = -1e30f, mr1 = -1e30f, l0 = 0.f, l1 = 0.f;

    const int nTiles = 2 * qt + 2;

    auto stage = [&](int kt, float* Kd, float* Vd) {
        const int k0 = kt * BN;
        #pragma unroll
        for (int t = 0; t < 4; ++t) {
            const int rr = srr[t];
            cp16((uint32_t)__cvta_generic_to_shared(&Kd[rr * RST + scc]),
                 Kp + (size_t)(k0 + rr) * RS + scc);
            cp16((uint32_t)__cvta_generic_to_shared(&Vd[rr * RST + scc]),
                 Vp + (size_t)(k0 + rr) * RS + scc);
        }
        asm volatile("cp.async.commit_group;\n" ::: "memory");
    };

    stage(0, rawK[0], rawV[0]);
    stage(1, rawK[1], rawV[1]);

    for (int kt = 0; kt < nTiles; ++kt) {
        const int k0 = kt * BN;
        const float* Kr = rawK[kt & 1];
        const float* Vr = rawV[kt & 1];

        if (kt + 1 < nTiles)
            asm volatile("cp.async.wait_group 1;\n" ::: "memory");
        else
            asm volatile("cp.async.wait_group 0;\n" ::: "memory");
        __syncthreads();   // raw[kt&1] ready AND conv bufs free (prev compute done)

        // ---- convert pass: raw -> Kh/Kl/Vh (once per tile) ----
        #pragma unroll
        for (int t = 0; t < 4; ++t) {
            const int rr = srr[t];
            float4 kf = *reinterpret_cast<const float4*>(&Kr[rr * RST + scc]);
            uint4 khv = { f2tf(kf.x), f2tf(kf.y), f2tf(kf.z), f2tf(kf.w) };
            uint4 klv = { f2tf(kf.x - __uint_as_float(khv.x)),
                          f2tf(kf.y - __uint_as_float(khv.y)),
                          f2tf(kf.z - __uint_as_float(khv.z)),
                          f2tf(kf.w - __uint_as_float(khv.w)) };
            *reinterpret_cast<uint4*>(&Kh[rr * KST + scc]) = khv;
            *reinterpret_cast<uint4*>(&Kl[rr * KST + scc]) = klv;
            float4 vf = *reinterpret_cast<const float4*>(&Vr[rr * RST + scc]);
            uint4 vu = { f2tf(vf.x), f2tf(vf.y), f2tf(vf.z), f2tf(vf.w) };
            *reinterpret_cast<uint4*>(&Vh[rr * VST + scc]) = vu;
        }
        __syncthreads();

        if (kt + 2 < nTiles)                  // raw[kt&1] now free
            stage(kt + 2, rawK[kt & 1], rawV[kt & 1]);

        // ---- S = Q K^T (log2 domain), 3xTF32 ----
        float s[8][4];
        #pragma unroll
        for (int j = 0; j < 8; ++j)
            #pragma unroll
            for (int i = 0; i < 4; ++i) s[j][i] = 0.f;

        #pragma unroll
        for (int kk = 0; kk < 8; ++kk) {
            #pragma unroll
            for (int j = 0; j < 8; ++j) {
                const int ko = (j * 8 + r) * KST + kk * 8 + c;
                uint32_t bh0 = Kh[ko], bh1 = Kh[ko + 4];
                uint32_t bl0 = Kl[ko], bl1 = Kl[ko + 4];
                mma_tf32(s[j], qh[kk][0], qh[kk][1], qh[kk][2], qh[kk][3], bh0, bh1);
                mma_tf32(s[j], ql[kk][0], ql[kk][1], ql[kk][2], ql[kk][3], bh0, bh1);
                mma_tf32(s[j], qh[kk][0], qh[kk][1], qh[kk][2], qh[kk][3], bl0, bl1);
            }
        }

        // ---- causal mask ----
        if (kt >= 2 * qt) {
            #pragma unroll
            for (int j = 0; j < 8; ++j) {
                int n = k0 + j * 8 + 2 * c;
                if (n     > m_lo)     s[j][0] = -1e30f;
                if (n + 1 > m_lo)     s[j][1] = -1e30f;
                if (n     > m_lo + 8) s[j][2] = -1e30f;
                if (n + 1 > m_lo + 8) s[j][3] = -1e30f;
            }
        }

        // ---- online softmax (log2 domain, rows r and r+8) ----
        float mx0 = -1e30f, mx1 = -1e30f;
        #pragma unroll
        for (int j = 0; j < 8; ++j) {
            mx0 = fmaxf(mx0, fmaxf(s[j][0], s[j][1]));
            mx1 = fmaxf(mx1, fmaxf(s[j][2], s[j][3]));
        }
        mx0 = fmaxf(mx0, __shfl_xor_sync(0xffffffffu, mx0, 1));
        mx0 = fmaxf(mx0, __shfl_xor_sync(0xffffffffu, mx0, 2));
        mx1 = fmaxf(mx1, __shfl_xor_sync(0xffffffffu, mx1, 1));
        mx1 = fmaxf(mx1, __shfl_xor_sync(0xffffffffu, mx1, 2));

        float mn0 = fmaxf(mr0, mx0), mn1 = fmaxf(mr1, mx1);
        float al0 = ex2(mr0 - mn0), al1 = ex2(mr1 - mn1);
        float sum0 = 0.f, sum1 = 0.f;
        #pragma unroll
        for (int j = 0; j < 8; ++j) {
            s[j][0] = ex2(s[j][0] - mn0);
            s[j][1] = ex2(s[j][1] - mn0);
            s[j][2] = ex2(s[j][2] - mn1);
            s[j][3] = ex2(s[j][3] - mn1);
            sum0 += s[j][0] + s[j][1];
            sum1 += s[j][2] + s[j][3];
        }
        sum0 += __shfl_xor_sync(0xffffffffu, sum0, 1);
        sum0 += __shfl_xor_sync(0xffffffffu, sum0, 2);
        sum1 += __shfl_xor_sync(0xffffffffu, sum1, 1);
        sum1 += __shfl_xor_sync(0xffffffffu, sum1, 2);

        l0 = l0 * al0 + sum0;
        l1 = l1 * al1 + sum1;
        mr0 = mn0; mr1 = mn1;

        #pragma unroll
        for (int j = 0; j < 8; ++j) {
            acc[j][0] *= al0; acc[j][1] *= al0;
            acc[j][2] *= al1; acc[j][3] *= al1;
        }

        // ---- O += P V : re-fragment P via shuffles, split-A tf32 ----
        const int src_lo = (lane & ~3) | (c >> 1);
        const int src_hi = src_lo + 2;
        const bool odd = (c & 1);
        #pragma unroll
        for (int kk = 0; kk < 8; ++kk) {
            float v00 = __shfl_sync(0xffffffffu, s[kk][0], src_lo);
            float v01 = __shfl_sync(0xffffffffu, s[kk][1], src_lo);
            float v10 = __shfl_sync(0xffffffffu, s[kk][0], src_hi);
            float v11 = __shfl_sync(0xffffffffu, s[kk][1], src_hi);
            float v20 = __shfl_sync(0xffffffffu, s[kk][2], src_lo);
            float v21 = __shfl_sync(0xffffffffu, s[kk][3], src_lo);
            float v30 = __shfl_sync(0xffffffffu, s[kk][2], src_hi);
            float v31 = __shfl_sync(0xffffffffu, s[kk][3], src_hi);
            float p0 = odd ? v01 : v00;
            float p1 = odd ? v21 : v20;
            float p2 = odd ? v11 : v10;
            float p3 = odd ? v31 : v30;
            uint32_t ph0 = f2tf(p0), pl0 = f2tf(p0 - __uint_as_float(ph0));
            uint32_t ph1 = f2tf(p1), pl1 = f2tf(p1 - __uint_as_float(ph1));
            uint32_t ph2 = f2tf(p2), pl2 = f2tf(p2 - __uint_as_float(ph2));
            uint32_t ph3 = f2tf(p3), pl3 = f2tf(p3 - __uint_as_float(ph3));
            #pragma unroll
            for (int jj = 0; jj < 8; ++jj) {
                uint32_t b0 = Vh[(kk * 8 + c) * VST + jj * 8 + r];
                uint32_t b1 = Vh[(kk * 8 + 4 + c) * VST + jj * 8 + r];
                mma_tf32(acc[jj], ph0, ph1, ph2, ph3, b0, b1);
                mma_tf32(acc[jj], pl0, pl1, pl2, pl3, b0, b1);
            }
        }
    }

    // ---- epilogue ----
    const float inv0 = 1.f / l0, inv1 = 1.f / l1;
    #pragma unroll
    for (int jj = 0; jj < 8; ++jj) {
        float2 o0 = { acc[jj][0] * inv0, acc[jj][1] * inv0 };
        float2 o1 = { acc[jj][2] * inv1, acc[jj][3] * inv1 };
        *reinterpret_cast<float2*>(Op + (size_t)m_lo * RS + jj * 8 + 2 * c) = o0;
        *reinterpret_cast<float2*>(Op + (size_t)(m_lo + 8) * RS + jj * 8 + 2 * c) = o1;
    }
}

extern "C" void kernel_launch(void* const* d_in, const int* in_sizes, int n_in,
                              void* d_out, int out_size)
{
    const float* Q = (const float*)d_in[0];
    const float* K = (const float*)d_in[1];
    const float* V = (const float*)d_in[2];
    // d_in[3] = attn_mask (causal triu(k=1)) — applied analytically in-kernel.
    float* O = (float*)d_out;

    cudaFuncSetAttribute(attn_kernel, cudaFuncAttributeMaxDynamicSharedMemorySize,
                         SMEM_BYTES);
    dim3 grid(L_ / BM, H_, B_);   // 16 x 16 x 2
    attn_kernel<<<grid, NT, SMEM_BYTES>>>(Q, K, V, O);
}

// round 7
// speedup vs baseline: 1.3248x; 1.1492x over previous
#include <cuda_runtime.h>
#include <cstdint>

// Causal MHA, B=2, L=2048, H=16, E=64, fp32; reference scales scores by sqrt(E)=8.
// tf32 mma.sync flash-attention, error-compensated:
//   QK^T: 3xTF32 (qh*kh + ql*kh + qh*kl); PV: split-A (ph*v + pl*v).
// R6: BM=64, 128 threads/CTA -> 2 independent CTAs per SM (phase interleaving
// feeds the tensor pipe). Single-buffer staging with convert-at-store (R3 body),
// log2-domain softmax, reversed qt order for causal load balance.

#define NT 128
#define BM 64
#define BN 64
#define ED 64
#define KST 68   // K smem row stride (floats): conflict-free B-frag loads
#define VST 72   // V smem row stride (floats): conflict-free B-frag loads

static constexpr int B_ = 2, L_ = 2048, H_ = 16;
static constexpr int RS = H_ * ED;                              // 1024 floats/row
static constexpr int SMEM_UINTS = 2 * BN * KST + BN * VST;      // Kh, Kl, Vh
static constexpr int SMEM_BYTES = SMEM_UINTS * 4;               // 53248 B

__device__ __forceinline__ uint32_t f2tf(float f) {
    uint32_t r;
    asm("cvt.rna.tf32.f32 %0, %1;" : "=r"(r) : "f"(f));
    return r;
}

__device__ __forceinline__ float ex2(float x) {
    float y;
    asm("ex2.approx.f32 %0, %1;" : "=f"(y) : "f"(x));
    return y;
}

__device__ __forceinline__ void mma_tf32(float c[4],
                                         uint32_t a0, uint32_t a1, uint32_t a2, uint32_t a3,
                                         uint32_t b0, uint32_t b1) {
    asm volatile(
        "mma.sync.aligned.m16n8k8.row.col.f32.tf32.tf32.f32 "
        "{%0,%1,%2,%3}, {%4,%5,%6,%7}, {%8,%9}, {%0,%1,%2,%3};"
        : "+f"(c[0]), "+f"(c[1]), "+f"(c[2]), "+f"(c[3])
        : "r"(a0), "r"(a1), "r"(a2), "r"(a3), "r"(b0), "r"(b1));
}

__global__ __launch_bounds__(NT, 2) void attn_kernel(
    const float* __restrict__ Q, const float* __restrict__ K,
    const float* __restrict__ V, float* __restrict__ O)
{
    extern __shared__ uint32_t smu[];
    uint32_t* Kh = smu;                      // [BN][KST]
    uint32_t* Kl = Kh + BN * KST;            // [BN][KST]
    uint32_t* Vh = Kl + BN * KST;            // [BN][VST]

    const int tid  = threadIdx.x;
    const int lane = tid & 31;
    const int w    = tid >> 5;               // 0..3
    const int r    = lane >> 2;              // 0..7
    const int c    = lane & 3;               // 0..3
    // reversed mapping: heaviest q-tiles (largest qt) get lowest blockIdx
    const int qt = (int)gridDim.x - 1 - (int)blockIdx.x;
    const int h  = blockIdx.y, b = blockIdx.z;
    const int q0 = qt * BM;
    const int m_lo = q0 + w * 16 + r;
    const size_t base = ((size_t)b * L_ * H_ + h) * ED;
    const float* Qp = Q + base;
    const float* Kp = K + base;
    const float* Vp = V + base;
    float*       Op = O + base;

    // ---- Q A-fragments: scale 8*log2(e), hi/lo tf32 split, resident ----
    const float QS = 8.f * 1.4426950408889634f;
    uint32_t qh[8][4], ql[8][4];
    #pragma unroll
    for (int kk = 0; kk < 8; ++kk) {
        const float* p = Qp + (size_t)m_lo * RS + kk * 8 + c;
        float f0 = QS * p[0];
        float f1 = QS * p[8 * RS];
        float f2 = QS * p[4];
        float f3 = QS * p[8 * RS + 4];
        qh[kk][0] = f2tf(f0); ql[kk][0] = f2tf(f0 - __uint_as_float(qh[kk][0]));
        qh[kk][1] = f2tf(f1); ql[kk][1] = f2tf(f1 - __uint_as_float(qh[kk][1]));
        qh[kk][2] = f2tf(f2); ql[kk][2] = f2tf(f2 - __uint_as_float(qh[kk][2]));
        qh[kk][3] = f2tf(f3); ql[kk][3] = f2tf(f3 - __uint_as_float(qh[kk][3]));
    }

    float acc[8][4];
    #pragma unroll
    for (int j = 0; j < 8; ++j)
        #pragma unroll
        for (int i = 0; i < 4; ++i) acc[j][i] = 0.f;

    float mr0 = -1e30f, mr1 = -1e30f, l0 = 0.f, l1 = 0.f;

    const int nTiles = qt + 1;               // causal: kv tiles 0..qt
    for (int kt = 0; kt < nTiles; ++kt) {
        const int k0 = kt * BN;
        __syncthreads();                     // prev compute done before overwrite

        // ---- stage K (hi+lo) and V (hi), convert at store ----
        #pragma unroll
        for (int t = 0; t < 8; ++t) {
            int idx = tid + t * NT;          // 1024 float4 slots
            int rr = idx >> 4;
            int cc = (idx & 15) * 4;
            float4 kf = *reinterpret_cast<const float4*>(Kp + (size_t)(k0 + rr) * RS + cc);
            uint4 khv = { f2tf(kf.x), f2tf(kf.y), f2tf(kf.z), f2tf(kf.w) };
            uint4 klv = { f2tf(kf.x - __uint_as_float(khv.x)),
                          f2tf(kf.y - __uint_as_float(khv.y)),
                          f2tf(kf.z - __uint_as_float(khv.z)),
                          f2tf(kf.w - __uint_as_float(khv.w)) };
            *reinterpret_cast<uint4*>(&Kh[rr * KST + cc]) = khv;
            *reinterpret_cast<uint4*>(&Kl[rr * KST + cc]) = klv;
            float4 vf = *reinterpret_cast<const float4*>(Vp + (size_t)(k0 + rr) * RS + cc);
            uint4 vu = { f2tf(vf.x), f2tf(vf.y), f2tf(vf.z), f2tf(vf.w) };
            *reinterpret_cast<uint4*>(&Vh[rr * VST + cc]) = vu;
        }
        __syncthreads();

        // ---- S = Q K^T (log2 domain), 3xTF32 ----
        float s[8][4];
        #pragma unroll
        for (int j = 0; j < 8; ++j)
            #pragma unroll
            for (int i = 0; i < 4; ++i) s[j][i] = 0.f;

        #pragma unroll
        for (int kk = 0; kk < 8; ++kk) {
            #pragma unroll
            for (int j = 0; j < 8; ++j) {
                const int ko = (j * 8 + r) * KST + kk * 8 + c;
                uint32_t bh0 = Kh[ko], bh1 = Kh[ko + 4];
                uint32_t bl0 = Kl[ko], bl1 = Kl[ko + 4];
                mma_tf32(s[j], qh[kk][0], qh[kk][1], qh[kk][2], qh[kk][3], bh0, bh1);
                mma_tf32(s[j], ql[kk][0], ql[kk][1], ql[kk][2], ql[kk][3], bh0, bh1);
                mma_tf32(s[j], qh[kk][0], qh[kk][1], qh[kk][2], qh[kk][3], bl0, bl1);
            }
        }

        // ---- causal mask (diagonal tile only) ----
        if (kt == qt) {
            #pragma unroll
            for (int j = 0; j < 8; ++j) {
                int n = k0 + j * 8 + 2 * c;
                if (n     > m_lo)     s[j][0] = -1e30f;
                if (n + 1 > m_lo)     s[j][1] = -1e30f;
                if (n     > m_lo + 8) s[j][2] = -1e30f;
                if (n + 1 > m_lo + 8) s[j][3] = -1e30f;
            }
        }

        // ---- online softmax (log2 domain, rows r and r+8) ----
        float mx0 = -1e30f, mx1 = -1e30f;
        #pragma unroll
        for (int j = 0; j < 8; ++j) {
            mx0 = fmaxf(mx0, fmaxf(s[j][0], s[j][1]));
            mx1 = fmaxf(mx1, fmaxf(s[j][2], s[j][3]));
        }
        mx0 = fmaxf(mx0, __shfl_xor_sync(0xffffffffu, mx0, 1));
        mx0 = fmaxf(mx0, __shfl_xor_sync(0xffffffffu, mx0, 2));
        mx1 = fmaxf(mx1, __shfl_xor_sync(0xffffffffu, mx1, 1));
        mx1 = fmaxf(mx1, __shfl_xor_sync(0xffffffffu, mx1, 2));

        float mn0 = fmaxf(mr0, mx0), mn1 = fmaxf(mr1, mx1);
        float al0 = ex2(mr0 - mn0), al1 = ex2(mr1 - mn1);
        float sum0 = 0.f, sum1 = 0.f;
        #pragma unroll
        for (int j = 0; j < 8; ++j) {
            s[j][0] = ex2(s[j][0] - mn0);
            s[j][1] = ex2(s[j][1] - mn0);
            s[j][2] = ex2(s[j][2] - mn1);
            s[j][3] = ex2(s[j][3] - mn1);
            sum0 += s[j][0] + s[j][1];
            sum1 += s[j][2] + s[j][3];
        }
        sum0 += __shfl_xor_sync(0xffffffffu, sum0, 1);
        sum0 += __shfl_xor_sync(0xffffffffu, sum0, 2);
        sum1 += __shfl_xor_sync(0xffffffffu, sum1, 1);
        sum1 += __shfl_xor_sync(0xffffffffu, sum1, 2);

        l0 = l0 * al0 + sum0;
        l1 = l1 * al1 + sum1;
        mr0 = mn0; mr1 = mn1;

        #pragma unroll
        for (int j = 0; j < 8; ++j) {
            acc[j][0] *= al0; acc[j][1] *= al0;
            acc[j][2] *= al1; acc[j][3] *= al1;
        }

        // ---- O += P V : re-fragment P via shuffles, split-A tf32 ----
        const int src_lo = (lane & ~3) | (c >> 1);
        const int src_hi = src_lo + 2;
        const bool odd = (c & 1);
        #pragma unroll
        for (int kk = 0; kk < 8; ++kk) {
            float v00 = __shfl_sync(0xffffffffu, s[kk][0], src_lo);
            float v01 = __shfl_sync(0xffffffffu, s[kk][1], src_lo);
            float v10 = __shfl_sync(0xffffffffu, s[kk][0], src_hi);
            float v11 = __shfl_sync(0xffffffffu, s[kk][1], src_hi);
            float v20 = __shfl_sync(0xffffffffu, s[kk][2], src_lo);
            float v21 = __shfl_sync(0xffffffffu, s[kk][3], src_lo);
            float v30 = __shfl_sync(0xffffffffu, s[kk][2], src_hi);
            float v31 = __shfl_sync(0xffffffffu, s[kk][3], src_hi);
            float p0 = odd ? v01 : v00;
            float p1 = odd ? v21 : v20;
            float p2 = odd ? v11 : v10;
            float p3 = odd ? v31 : v30;
            uint32_t ph0 = f2tf(p0), pl0 = f2tf(p0 - __uint_as_float(ph0));
            uint32_t ph1 = f2tf(p1), pl1 = f2tf(p1 - __uint_as_float(ph1));
            uint32_t ph2 = f2tf(p2), pl2 = f2tf(p2 - __uint_as_float(ph2));
            uint32_t ph3 = f2tf(p3), pl3 = f2tf(p3 - __uint_as_float(ph3));
            #pragma unroll
            for (int jj = 0; jj < 8; ++jj) {
                uint32_t b0 = Vh[(kk * 8 + c) * VST + jj * 8 + r];
                uint32_t b1 = Vh[(kk * 8 + 4 + c) * VST + jj * 8 + r];
                mma_tf32(acc[jj], ph0, ph1, ph2, ph3, b0, b1);
                mma_tf32(acc[jj], pl0, pl1, pl2, pl3, b0, b1);
            }
        }
    }

    // ---- epilogue ----
    const float inv0 = 1.f / l0, inv1 = 1.f / l1;
    #pragma unroll
    for (int jj = 0; jj < 8; ++jj) {
        float2 o0 = { acc[jj][0] * inv0, acc[jj][1] * inv0 };
        float2 o1 = { acc[jj][2] * inv1, acc[jj][3] * inv1 };
        *reinterpret_cast<float2*>(Op + (size_t)m_lo * RS + jj * 8 + 2 * c) = o0;
        *reinterpret_cast<float2*>(Op + (size_t)(m_lo + 8) * RS + jj * 8 + 2 * c) = o1;
    }
}

extern "C" void kernel_launch(void* const* d_in, const int* in_sizes, int n_in,
                              void* d_out, int out_size)
{
    const float* Q = (const float*)d_in[0];
    const float* K = (const float*)d_in[1];
    const float* V = (const float*)d_in[2];
    // d_in[3] = attn_mask (causal triu(k=1)) — applied analytically in-kernel.
    float* O = (float*)d_out;

    cudaFuncSetAttribute(attn_kernel, cudaFuncAttributeMaxDynamicSharedMemorySize,
                         SMEM_BYTES);
    dim3 grid(L_ / BM, H_, B_);   // 32 x 16 x 2
    attn_kernel<<<grid, NT, SMEM_BYTES>>>(Q, K, V, O);
}

// round 8
// speedup vs baseline: 1.7796x; 1.3433x over previous
#include <cuda_runtime.h>
#include <cstdint>

// Causal MHA, B=2, L=2048, H=16, E=64, fp32; reference scales scores by sqrt(E)=8.
// R7: bf16 m16n8k16 mma.sync flash-attention with 2-level (hi/lo) splits:
//   QK^T: qh*kh + ql*kh + qh*kl   (missing term ~2^-16)
//   PV  : ph*vh + pl*vh + ph*vl
// C-fragment == A-fragment for k16 -> P re-fragmentation needs NO shuffles.
// BM=64, 128 threads, 2 CTAs/SM. V packed as seq-pairs via smem transpose pass.
// All smem layouts stride-36 uint32 -> conflict-free loads and stores.

#define NT 128
#define BM 64
#define BN 64
#define ED 64
#define ST 36    // uint32 row stride for Kh/Kl/Vh/Vl (bank = 4r+c, bijective)
#define RVST 68  // float row stride for raw V tile

static constexpr int B_ = 2, L_ = 2048, H_ = 16;
static constexpr int RS = H_ * ED;                   // 1024 floats per seq row
// smem (uint32): Kh,Kl,Vh,Vl: 64*36 each; Vr raw: 64*68 floats
static constexpr int SMEM_UINTS = 4 * BN * ST + BN * RVST;
static constexpr int SMEM_BYTES = SMEM_UINTS * 4;    // 54272 B

__device__ __forceinline__ uint32_t pack_bf16x2(float lo, float hi) {
    uint32_t d;   // PTX: first source -> upper half
    asm("cvt.rn.bf16x2.f32 %0, %1, %2;" : "=r"(d) : "f"(hi), "f"(lo));
    return d;
}
__device__ __forceinline__ float bf_lo(uint32_t u) { return __uint_as_float(u << 16); }
__device__ __forceinline__ float bf_hi(uint32_t u) { return __uint_as_float(u & 0xffff0000u); }

__device__ __forceinline__ float ex2(float x) {
    float y;
    asm("ex2.approx.f32 %0, %1;" : "=f"(y) : "f"(x));
    return y;
}

__device__ __forceinline__ void mma_bf16(float c[4],
                                         uint32_t a0, uint32_t a1, uint32_t a2, uint32_t a3,
                                         uint32_t b0, uint32_t b1) {
    asm volatile(
        "mma.sync.aligned.m16n8k16.row.col.f32.bf16.bf16.f32 "
        "{%0,%1,%2,%3}, {%4,%5,%6,%7}, {%8,%9}, {%0,%1,%2,%3};"
        : "+f"(c[0]), "+f"(c[1]), "+f"(c[2]), "+f"(c[3])
        : "r"(a0), "r"(a1), "r"(a2), "r"(a3), "r"(b0), "r"(b1));
}

__global__ __launch_bounds__(NT, 2) void attn_kernel(
    const float* __restrict__ Q, const float* __restrict__ K,
    const float* __restrict__ V, float* __restrict__ O)
{
    extern __shared__ uint32_t smu[];
    uint32_t* Kh = smu;                   // [64][ST]  (n rows, k-pair cols)
    uint32_t* Kl = Kh + BN * ST;
    uint32_t* Vh = Kl + BN * ST;          // [64][ST]  (e rows, n-pair cols)
    uint32_t* Vl = Vh + BN * ST;
    float*    Vr = reinterpret_cast<float*>(Vl + BN * ST);   // [64][RVST] raw V

    const int tid  = threadIdx.x;
    const int lane = tid & 31;
    const int w    = tid >> 5;            // 0..3
    const int r    = lane >> 2;           // 0..7  (groupID)
    const int c    = lane & 3;            // 0..3  (threadID in group)
    const int qt = (int)gridDim.x - 1 - (int)blockIdx.x;   // heavy tiles first
    const int h  = blockIdx.y, b = blockIdx.z;
    const int q0 = qt * BM;
    const int m_lo = q0 + w * 16 + r;
    const size_t base = ((size_t)b * L_ * H_ + h) * ED;
    const float* Qp = Q + base;
    const float* Kp = K + base;
    const float* Vp = V + base;
    float*       Op = O + base;

    // ---- Q A-fragments: scale 8*log2(e), bf16 hi/lo split, resident ----
    const float QS = 8.f * 1.4426950408889634f;
    uint32_t qh[4][4], ql[4][4];
    #pragma unroll
    for (int kk = 0; kk < 4; ++kk) {
        const float* p = Qp + (size_t)m_lo * RS + kk * 16 + 2 * c;
        float2 x0 = *reinterpret_cast<const float2*>(p);            // A[r][2c,2c+1]
        float2 x1 = *reinterpret_cast<const float2*>(p + 8 * RS);   // A[r+8][..]
        float2 x2 = *reinterpret_cast<const float2*>(p + 8);        // A[r][2c+8..]
        float2 x3 = *reinterpret_cast<const float2*>(p + 8 * RS + 8);
        float f[4][2] = { {QS*x0.x, QS*x0.y}, {QS*x1.x, QS*x1.y},
                          {QS*x2.x, QS*x2.y}, {QS*x3.x, QS*x3.y} };
        #pragma unroll
        for (int i = 0; i < 4; ++i) {
            uint32_t hh = pack_bf16x2(f[i][0], f[i][1]);
            qh[kk][i] = hh;
            ql[kk][i] = pack_bf16x2(f[i][0] - bf_lo(hh), f[i][1] - bf_hi(hh));
        }
    }

    float acc[8][4];
    #pragma unroll
    for (int j = 0; j < 8; ++j)
        #pragma unroll
        for (int i = 0; i < 4; ++i) acc[j][i] = 0.f;

    float mr0 = -1e30f, mr1 = -1e30f, l0 = 0.f, l1 = 0.f;

    // pass-B lane constants (V transpose/pack)
    const int cp = lane & 3;
    const int rp = lane >> 2;

    const int nTiles = qt + 1;
    for (int kt = 0; kt < nTiles; ++kt) {
        const int k0 = kt * BN;
        __syncthreads();                  // prev compute done before overwrite

        // ---- pass A: K convert-at-store (pairs along k); V raw to smem ----
        #pragma unroll
        for (int t = 0; t < 8; ++t) {
            int idx = tid + t * NT;       // 1024 float4 slots
            int rr = idx >> 4;
            int cc = (idx & 15) * 4;
            float4 kf = *reinterpret_cast<const float4*>(Kp + (size_t)(k0 + rr) * RS + cc);
            uint32_t h01 = pack_bf16x2(kf.x, kf.y);
            uint32_t h23 = pack_bf16x2(kf.z, kf.w);
            uint32_t l01 = pack_bf16x2(kf.x - bf_lo(h01), kf.y - bf_hi(h01));
            uint32_t l23 = pack_bf16x2(kf.z - bf_lo(h23), kf.w - bf_hi(h23));
            *reinterpret_cast<uint2*>(&Kh[rr * ST + (cc >> 1)]) = make_uint2(h01, h23);
            *reinterpret_cast<uint2*>(&Kl[rr * ST + (cc >> 1)]) = make_uint2(l01, l23);
            float4 vf = *reinterpret_cast<const float4*>(Vp + (size_t)(k0 + rr) * RS + cc);
            *reinterpret_cast<float4*>(&Vr[rr * RVST + cc]) = vf;
        }
        __syncthreads();

        // ---- pass B: transpose/pack V -> Vh/Vl [e][n-pair] ----
        #pragma unroll
        for (int t = 0; t < 16; ++t) {
            int nb = t & 7;
            int eb = w + ((t >> 3) << 2);        // w or w+4
            int np = nb * 4 + cp;                // 0..31
            int e  = eb * 8 + rp;                // 0..63
            float v0 = Vr[(2 * np)     * RVST + e];
            float v1 = Vr[(2 * np + 1) * RVST + e];
            uint32_t hh = pack_bf16x2(v0, v1);
            Vh[e * ST + np] = hh;
            Vl[e * ST + np] = pack_bf16x2(v0 - bf_lo(hh), v1 - bf_hi(hh));
        }
        __syncthreads();

        // ---- S = Q K^T (log2 domain), 3-term bf16 ----
        float s[8][4];
        #pragma unroll
        for (int j = 0; j < 8; ++j)
            #pragma unroll
            for (int i = 0; i < 4; ++i) s[j][i] = 0.f;

        #pragma unroll
        for (int kk = 0; kk < 4; ++kk) {
            #pragma unroll
            for (int j = 0; j < 8; ++j) {
                const int ko = (j * 8 + r) * ST + kk * 8 + c;
                uint32_t bh0 = Kh[ko], bh1 = Kh[ko + 4];
                uint32_t bl0 = Kl[ko], bl1 = Kl[ko + 4];
                mma_bf16(s[j], qh[kk][0], qh[kk][1], qh[kk][2], qh[kk][3], bh0, bh1);
                mma_bf16(s[j], ql[kk][0], ql[kk][1], ql[kk][2], ql[kk][3], bh0, bh1);
                mma_bf16(s[j], qh[kk][0], qh[kk][1], qh[kk][2], qh[kk][3], bl0, bl1);
            }
        }

        // ---- causal mask (diagonal tile only) ----
        if (kt == qt) {
            #pragma unroll
            for (int j = 0; j < 8; ++j) {
                int n = k0 + j * 8 + 2 * c;
                if (n     > m_lo)     s[j][0] = -1e30f;
                if (n + 1 > m_lo)     s[j][1] = -1e30f;
                if (n     > m_lo + 8) s[j][2] = -1e30f;
                if (n + 1 > m_lo + 8) s[j][3] = -1e30f;
            }
        }

        // ---- online softmax (log2 domain, rows r and r+8) ----
        float mx0 = -1e30f, mx1 = -1e30f;
        #pragma unroll
        for (int j = 0; j < 8; ++j) {
            mx0 = fmaxf(mx0, fmaxf(s[j][0], s[j][1]));
            mx1 = fmaxf(mx1, fmaxf(s[j][2], s[j][3]));
        }
        mx0 = fmaxf(mx0, __shfl_xor_sync(0xffffffffu, mx0, 1));
        mx0 = fmaxf(mx0, __shfl_xor_sync(0xffffffffu, mx0, 2));
        mx1 = fmaxf(mx1, __shfl_xor_sync(0xffffffffu, mx1, 1));
        mx1 = fmaxf(mx1, __shfl_xor_sync(0xffffffffu, mx1, 2));

        float mn0 = fmaxf(mr0, mx0), mn1 = fmaxf(mr1, mx1);
        float al0 = ex2(mr0 - mn0), al1 = ex2(mr1 - mn1);
        float sum0 = 0.f, sum1 = 0.f;
        #pragma unroll
        for (int j = 0; j < 8; ++j) {
            s[j][0] = ex2(s[j][0] - mn0);
            s[j][1] = ex2(s[j][1] - mn0);
            s[j][2] = ex2(s[j][2] - mn1);
            s[j][3] = ex2(s[j][3] - mn1);
            sum0 += s[j][0] + s[j][1];
            sum1 += s[j][2] + s[j][3];
        }
        sum0 += __shfl_xor_sync(0xffffffffu, sum0, 1);
        sum0 += __shfl_xor_sync(0xffffffffu, sum0, 2);
        sum1 += __shfl_xor_sync(0xffffffffu, sum1, 1);
        sum1 += __shfl_xor_sync(0xffffffffu, sum1, 2);

        l0 = l0 * al0 + sum0;
        l1 = l1 * al1 + sum1;
        mr0 = mn0; mr1 = mn1;

        #pragma unroll
        for (int j = 0; j < 8; ++j) {
            acc[j][0] *= al0; acc[j][1] *= al0;
            acc[j][2] *= al1; acc[j][3] *= al1;
        }

        // ---- O += P V : C-frag == A-frag (no shuffles), 3-term bf16 ----
        #pragma unroll
        for (int kk = 0; kk < 4; ++kk) {
            // A-frag from S tiles j=2kk (k 0..7) and j=2kk+1 (k 8..15)
            float s00 = s[2*kk][0],   s01 = s[2*kk][1];
            float s10 = s[2*kk][2],   s11 = s[2*kk][3];
            float s20 = s[2*kk+1][0], s21 = s[2*kk+1][1];
            float s30 = s[2*kk+1][2], s31 = s[2*kk+1][3];
            uint32_t ph0 = pack_bf16x2(s00, s01);
            uint32_t ph1 = pack_bf16x2(s10, s11);
            uint32_t ph2 = pack_bf16x2(s20, s21);
            uint32_t ph3 = pack_bf16x2(s30, s31);
            uint32_t pl0 = pack_bf16x2(s00 - bf_lo(ph0), s01 - bf_hi(ph0));
            uint32_t pl1 = pack_bf16x2(s10 - bf_lo(ph1), s11 - bf_hi(ph1));
            uint32_t pl2 = pack_bf16x2(s20 - bf_lo(ph2), s21 - bf_hi(ph2));
            uint32_t pl3 = pack_bf16x2(s30 - bf_lo(ph3), s31 - bf_hi(ph3));
            #pragma unroll
            for (int jj = 0; jj < 8; ++jj) {
                const int vo = (jj * 8 + r) * ST + kk * 8 + c;
                uint32_t bh0 = Vh[vo], bh1 = Vh[vo + 4];
                uint32_t bl0 = Vl[vo], bl1 = Vl[vo + 4];
                mma_bf16(acc[jj], ph0, ph1, ph2, ph3, bh0, bh1);
                mma_bf16(acc[jj], pl0, pl1, pl2, pl3, bh0, bh1);
                mma_bf16(acc[jj], ph0, ph1, ph2, ph3, bl0, bl1);
            }
        }
    }

    // ---- epilogue ----
    const float inv0 = 1.f / l0, inv1 = 1.f / l1;
    #pragma unroll
    for (int jj = 0; jj < 8; ++jj) {
        float2 o0 = { acc[jj][0] * inv0, acc[jj][1] * inv0 };
        float2 o1 = { acc[jj][2] * inv1, acc[jj][3] * inv1 };
        *reinterpret_cast<float2*>(Op + (size_t)m_lo * RS + jj * 8 + 2 * c) = o0;
        *reinterpret_cast<float2*>(Op + (size_t)(m_lo + 8) * RS + jj * 8 + 2 * c) = o1;
    }
}

extern "C" void kernel_launch(void* const* d_in, const int* in_sizes, int n_in,
                              void* d_out, int out_size)
{
    const float* Q = (const float*)d_in[0];
    const float* K = (const float*)d_in[1];
    const float* V = (const float*)d_in[2];
    // d_in[3] = attn_mask (causal triu(k=1)) — applied analytically in-kernel.
    float* O = (float*)d_out;

    cudaFuncSetAttribute(attn_kernel, cudaFuncAttributeMaxDynamicSharedMemorySize,
                         SMEM_BYTES);
    dim3 grid(L_ / BM, H_, B_);   // 32 x 16 x 2
    attn_kernel<<<grid, NT, SMEM_BYTES>>>(Q, K, V, O);
}

// round 9
// speedup vs baseline: 1.8795x; 1.0561x over previous
#include <cuda_runtime.h>
#include <cstdint>

// Causal MHA, B=2, L=2048, H=16, E=64, fp32; reference scales scores by sqrt(E)=8.
// R8: bf16 m16n8k16 flash-attention (R7 body) with:
//   - __launch_bounds__(128, 3): 3 CTAs/SM for phase interleaving
//   - deferred l-reduction (per-lane partial sums, reduced once in epilogue)
// QK^T: qh*kh + ql*kh + qh*kl; PV: ph*vh + pl*vh + ph*vl (missing terms ~2^-16).
// C-frag == A-frag for k16 -> no shuffles in P re-fragmentation.

#define NT 128
#define BM 64
#define BN 64
#define ED 64
#define ST 36    // uint32 row stride for Kh/Kl/Vh/Vl (conflict-free)
#define RVST 68  // float row stride for raw V tile

static constexpr int B_ = 2, L_ = 2048, H_ = 16;
static constexpr int RS = H_ * ED;                   // 1024 floats per seq row
static constexpr int SMEM_UINTS = 4 * BN * ST + BN * RVST;
static constexpr int SMEM_BYTES = SMEM_UINTS * 4;    // 54272 B

__device__ __forceinline__ uint32_t pack_bf16x2(float lo, float hi) {
    uint32_t d;   // PTX: first source -> upper half
    asm("cvt.rn.bf16x2.f32 %0, %1, %2;" : "=r"(d) : "f"(hi), "f"(lo));
    return d;
}
__device__ __forceinline__ float bf_lo(uint32_t u) { return __uint_as_float(u << 16); }
__device__ __forceinline__ float bf_hi(uint32_t u) { return __uint_as_float(u & 0xffff0000u); }

__device__ __forceinline__ float ex2(float x) {
    float y;
    asm("ex2.approx.f32 %0, %1;" : "=f"(y) : "f"(x));
    return y;
}

__device__ __forceinline__ void mma_bf16(float c[4],
                                         uint32_t a0, uint32_t a1, uint32_t a2, uint32_t a3,
                                         uint32_t b0, uint32_t b1) {
    asm volatile(
        "mma.sync.aligned.m16n8k16.row.col.f32.bf16.bf16.f32 "
        "{%0,%1,%2,%3}, {%4,%5,%6,%7}, {%8,%9}, {%0,%1,%2,%3};"
        : "+f"(c[0]), "+f"(c[1]), "+f"(c[2]), "+f"(c[3])
        : "r"(a0), "r"(a1), "r"(a2), "r"(a3), "r"(b0), "r"(b1));
}

__global__ __launch_bounds__(NT, 3) void attn_kernel(
    const float* __restrict__ Q, const float* __restrict__ K,
    const float* __restrict__ V, float* __restrict__ O)
{
    extern __shared__ uint32_t smu[];
    uint32_t* Kh = smu;                   // [64][ST]  (n rows, k-pair cols)
    uint32_t* Kl = Kh + BN * ST;
    uint32_t* Vh = Kl + BN * ST;          // [64][ST]  (e rows, n-pair cols)
    uint32_t* Vl = Vh + BN * ST;
    float*    Vr = reinterpret_cast<float*>(Vl + BN * ST);   // [64][RVST] raw V

    const int tid  = threadIdx.x;
    const int lane = tid & 31;
    const int w    = tid >> 5;            // 0..3
    const int r    = lane >> 2;           // 0..7
    const int c    = lane & 3;            // 0..3
    const int qt = (int)gridDim.x - 1 - (int)blockIdx.x;   // heavy tiles first
    const int h  = blockIdx.y, b = blockIdx.z;
    const int q0 = qt * BM;
    const int m_lo = q0 + w * 16 + r;
    const size_t base = ((size_t)b * L_ * H_ + h) * ED;
    const float* Qp = Q + base;
    const float* Kp = K + base;
    const float* Vp = V + base;
    float*       Op = O + base;

    // ---- Q A-fragments: scale 8*log2(e), bf16 hi/lo split, resident ----
    const float QS = 8.f * 1.4426950408889634f;
    uint32_t qh[4][4], ql[4][4];
    #pragma unroll
    for (int kk = 0; kk < 4; ++kk) {
        const float* p = Qp + (size_t)m_lo * RS + kk * 16 + 2 * c;
        float2 x0 = *reinterpret_cast<const float2*>(p);
        float2 x1 = *reinterpret_cast<const float2*>(p + 8 * RS);
        float2 x2 = *reinterpret_cast<const float2*>(p + 8);
        float2 x3 = *reinterpret_cast<const float2*>(p + 8 * RS + 8);
        float f[4][2] = { {QS*x0.x, QS*x0.y}, {QS*x1.x, QS*x1.y},
                          {QS*x2.x, QS*x2.y}, {QS*x3.x, QS*x3.y} };
        #pragma unroll
        for (int i = 0; i < 4; ++i) {
            uint32_t hh = pack_bf16x2(f[i][0], f[i][1]);
            qh[kk][i] = hh;
            ql[kk][i] = pack_bf16x2(f[i][0] - bf_lo(hh), f[i][1] - bf_hi(hh));
        }
    }

    float acc[8][4];
    #pragma unroll
    for (int j = 0; j < 8; ++j)
        #pragma unroll
        for (int i = 0; i < 4; ++i) acc[j][i] = 0.f;

    float mr0 = -1e30f, mr1 = -1e30f;
    float l0 = 0.f, l1 = 0.f;             // PER-LANE partial sums (reduced at end)

    const int cp = lane & 3;
    const int rp = lane >> 2;

    const int nTiles = qt + 1;
    for (int kt = 0; kt < nTiles; ++kt) {
        const int k0 = kt * BN;
        __syncthreads();

        // ---- pass A: K convert-at-store; V raw to smem ----
        #pragma unroll
        for (int t = 0; t < 8; ++t) {
            int idx = tid + t * NT;
            int rr = idx >> 4;
            int cc = (idx & 15) * 4;
            float4 kf = *reinterpret_cast<const float4*>(Kp + (size_t)(k0 + rr) * RS + cc);
            uint32_t h01 = pack_bf16x2(kf.x, kf.y);
            uint32_t h23 = pack_bf16x2(kf.z, kf.w);
            uint32_t l01 = pack_bf16x2(kf.x - bf_lo(h01), kf.y - bf_hi(h01));
            uint32_t l23 = pack_bf16x2(kf.z - bf_lo(h23), kf.w - bf_hi(h23));
            *reinterpret_cast<uint2*>(&Kh[rr * ST + (cc >> 1)]) = make_uint2(h01, h23);
            *reinterpret_cast<uint2*>(&Kl[rr * ST + (cc >> 1)]) = make_uint2(l01, l23);
            float4 vf = *reinterpret_cast<const float4*>(Vp + (size_t)(k0 + rr) * RS + cc);
            *reinterpret_cast<float4*>(&Vr[rr * RVST + cc]) = vf;
        }
        __syncthreads();

        // ---- pass B: transpose/pack V -> Vh/Vl [e][n-pair] ----
        #pragma unroll
        for (int t = 0; t < 16; ++t) {
            int nb = t & 7;
            int eb = w + ((t >> 3) << 2);
            int np = nb * 4 + cp;
            int e  = eb * 8 + rp;
            float v0 = Vr[(2 * np)     * RVST + e];
            float v1 = Vr[(2 * np + 1) * RVST + e];
            uint32_t hh = pack_bf16x2(v0, v1);
            Vh[e * ST + np] = hh;
            Vl[e * ST + np] = pack_bf16x2(v0 - bf_lo(hh), v1 - bf_hi(hh));
        }
        __syncthreads();

        // ---- S = Q K^T (log2 domain), 3-term bf16 ----
        float s[8][4];
        #pragma unroll
        for (int j = 0; j < 8; ++j)
            #pragma unroll
            for (int i = 0; i < 4; ++i) s[j][i] = 0.f;

        #pragma unroll
        for (int kk = 0; kk < 4; ++kk) {
            #pragma unroll
            for (int j = 0; j < 8; ++j) {
                const int ko = (j * 8 + r) * ST + kk * 8 + c;
                uint32_t bh0 = Kh[ko], bh1 = Kh[ko + 4];
                uint32_t bl0 = Kl[ko], bl1 = Kl[ko + 4];
                mma_bf16(s[j], qh[kk][0], qh[kk][1], qh[kk][2], qh[kk][3], bh0, bh1);
                mma_bf16(s[j], ql[kk][0], ql[kk][1], ql[kk][2], ql[kk][3], bh0, bh1);
                mma_bf16(s[j], qh[kk][0], qh[kk][1], qh[kk][2], qh[kk][3], bl0, bl1);
            }
        }

        // ---- causal mask (diagonal tile only) ----
        if (kt == qt) {
            #pragma unroll
            for (int j = 0; j < 8; ++j) {
                int n = k0 + j * 8 + 2 * c;
                if (n     > m_lo)     s[j][0] = -1e30f;
                if (n + 1 > m_lo)     s[j][1] = -1e30f;
                if (n     > m_lo + 8) s[j][2] = -1e30f;
                if (n + 1 > m_lo + 8) s[j][3] = -1e30f;
            }
        }

        // ---- online softmax: only MAX is reduced; l stays per-lane ----
        float mx0 = -1e30f, mx1 = -1e30f;
        #pragma unroll
        for (int j = 0; j < 8; ++j) {
            mx0 = fmaxf(mx0, fmaxf(s[j][0], s[j][1]));
            mx1 = fmaxf(mx1, fmaxf(s[j][2], s[j][3]));
        }
        mx0 = fmaxf(mx0, __shfl_xor_sync(0xffffffffu, mx0, 1));
        mx0 = fmaxf(mx0, __shfl_xor_sync(0xffffffffu, mx0, 2));
        mx1 = fmaxf(mx1, __shfl_xor_sync(0xffffffffu, mx1, 1));
        mx1 = fmaxf(mx1, __shfl_xor_sync(0xffffffffu, mx1, 2));

        float mn0 = fmaxf(mr0, mx0), mn1 = fmaxf(mr1, mx1);
        float al0 = ex2(mr0 - mn0), al1 = ex2(mr1 - mn1);
        float sum0 = 0.f, sum1 = 0.f;
        #pragma unroll
        for (int j = 0; j < 8; ++j) {
            s[j][0] = ex2(s[j][0] - mn0);
            s[j][1] = ex2(s[j][1] - mn0);
            s[j][2] = ex2(s[j][2] - mn1);
            s[j][3] = ex2(s[j][3] - mn1);
            sum0 += s[j][0] + s[j][1];
            sum1 += s[j][2] + s[j][3];
        }
        l0 = l0 * al0 + sum0;             // per-lane partial; reduce in epilogue
        l1 = l1 * al1 + sum1;
        mr0 = mn0; mr1 = mn1;

        #pragma unroll
        for (int j = 0; j < 8; ++j) {
            acc[j][0] *= al0; acc[j][1] *= al0;
            acc[j][2] *= al1; acc[j][3] *= al1;
        }

        // ---- O += P V : C-frag == A-frag, 3-term bf16 ----
        #pragma unroll
        for (int kk = 0; kk < 4; ++kk) {
            float s00 = s[2*kk][0],   s01 = s[2*kk][1];
            float s10 = s[2*kk][2],   s11 = s[2*kk][3];
            float s20 = s[2*kk+1][0], s21 = s[2*kk+1][1];
            float s30 = s[2*kk+1][2], s31 = s[2*kk+1][3];
            uint32_t ph0 = pack_bf16x2(s00, s01);
            uint32_t ph1 = pack_bf16x2(s10, s11);
            uint32_t ph2 = pack_bf16x2(s20, s21);
            uint32_t ph3 = pack_bf16x2(s30, s31);
            uint32_t pl0 = pack_bf16x2(s00 - bf_lo(ph0), s01 - bf_hi(ph0));
            uint32_t pl1 = pack_bf16x2(s10 - bf_lo(ph1), s11 - bf_hi(ph1));
            uint32_t pl2 = pack_bf16x2(s20 - bf_lo(ph2), s21 - bf_hi(ph2));
            uint32_t pl3 = pack_bf16x2(s30 - bf_lo(ph3), s31 - bf_hi(ph3));
            #pragma unroll
            for (int jj = 0; jj < 8; ++jj) {
                const int vo = (jj * 8 + r) * ST + kk * 8 + c;
                uint32_t bh0 = Vh[vo], bh1 = Vh[vo + 4];
                uint32_t bl0 = Vl[vo], bl1 = Vl[vo + 4];
                mma_bf16(acc[jj], ph0, ph1, ph2, ph3, bh0, bh1);
                mma_bf16(acc[jj], pl0, pl1, pl2, pl3, bh0, bh1);
                mma_bf16(acc[jj], ph0, ph1, ph2, ph3, bl0, bl1);
            }
        }
    }

    // ---- epilogue: reduce l across the quad, normalize, store ----
    l0 += __shfl_xor_sync(0xffffffffu, l0, 1);
    l0 += __shfl_xor_sync(0xffffffffu, l0, 2);
    l1 += __shfl_xor_sync(0xffffffffu, l1, 1);
    l1 += __shfl_xor_sync(0xffffffffu, l1, 2);
    const float inv0 = 1.f / l0, inv1 = 1.f / l1;
    #pragma unroll
    for (int jj = 0; jj < 8; ++jj) {
        float2 o0 = { acc[jj][0] * inv0, acc[jj][1] * inv0 };
        float2 o1 = { acc[jj][2] * inv1, acc[jj][3] * inv1 };
        *reinterpret_cast<float2*>(Op + (size_t)m_lo * RS + jj * 8 + 2 * c) = o0;
        *reinterpret_cast<float2*>(Op + (size_t)(m_lo + 8) * RS + jj * 8 + 2 * c) = o1;
    }
}

extern "C" void kernel_launch(void* const* d_in, const int* in_sizes, int n_in,
                              void* d_out, int out_size)
{
    const float* Q = (const float*)d_in[0];
    const float* K = (const float*)d_in[1];
    const float* V = (const float*)d_in[2];
    // d_in[3] = attn_mask (causal triu(k=1)) — applied analytically in-kernel.
    float* O = (float*)d_out;

    cudaFuncSetAttribute(attn_kernel, cudaFuncAttributeMaxDynamicSharedMemorySize,
                         SMEM_BYTES);
    dim3 grid(L_ / BM, H_, B_);   // 32 x 16 x 2
    attn_kernel<<<grid, NT, SMEM_BYTES>>>(Q, K, V, O);
}